// round 7
// baseline (speedup 1.0000x reference)
#include <cuda_runtime.h>
#include <math.h>

// ---------------- configuration ----------------
#define TPB2 128      // threads per block in pair kernel
#define IT   4        // i's per thread (2 packed f32x2 lanes)
#define ITP  (IT/2)   // packed accumulators per thread
#define JC   1024     // j-chunk size (smem tile)
#define MAXN 8192
#define NJC  (MAXN / JC)                  // 8 j-chunks
#define NIG  (MAXN / (TPB2 * IT))         // 16 i-groups
#define NUV  (NIG * NJC)                  // 128 uv partials
#define RTPB 256
#define RWARPS (RTPB / 32)                // 8 warps
#define RBLK (MAXN / RTPB)                // 32 rowred blocks (== warp size!)
#define NSUM 11
#define ABSMASK 0x7FFFFFFF7FFFFFFFULL

// ---------------- device scratch (static, no allocation) ----------------
__device__ float  g_apart[NJC * MAXN];     // per-(jchunk,i) partial of alpha'
__device__ float  g_bpart[NJC * MAXN];     // per-(jchunk,i) partial of beta'
__device__ double g_uvpart[NUV];           // per-block partial of S_uv
__device__ double g_red[RBLK * NSUM];      // per-rowred-block partial sums
__device__ unsigned int g_counter = 0;     // last-block ticket (reset by k_pairs)

// ---------------- f32x2 helpers ----------------
typedef unsigned long long u64;

__device__ __forceinline__ u64 f2pack(float x) {
    u64 r; asm("mov.b64 %0, {%1, %1};" : "=l"(r) : "f"(x)); return r;
}
__device__ __forceinline__ u64 add2(u64 a, u64 b) {
    u64 r; asm("add.rn.f32x2 %0, %1, %2;" : "=l"(r) : "l"(a), "l"(b)); return r;
}
__device__ __forceinline__ u64 mul2(u64 a, u64 b) {
    u64 r; asm("mul.rn.f32x2 %0, %1, %2;" : "=l"(r) : "l"(a), "l"(b)); return r;
}
__device__ __forceinline__ u64 fma2(u64 a, u64 b, u64 c) {
    u64 r; asm("fma.rn.f32x2 %0, %1, %2, %3;" : "=l"(r) : "l"(a), "l"(b), "l"(c)); return r;
}
__device__ __forceinline__ void unpack2(u64 v, float& lo, float& hi) {
    asm("mov.b64 {%0, %1}, %2;" : "=f"(lo), "=f"(hi) : "l"(v));
}

// ---------------- block reduction (double), generic ----------------
__device__ __forceinline__ double blockReduceSumD(double val) {
    __shared__ double shared[32];
    __syncthreads();
    int lane = threadIdx.x & 31;
    int wid  = threadIdx.x >> 5;
    #pragma unroll
    for (int o = 16; o > 0; o >>= 1)
        val += __shfl_down_sync(0xffffffffu, val, o);
    if (lane == 0) shared[wid] = val;
    __syncthreads();
    int nwarps = (blockDim.x + 31) >> 5;
    val = (threadIdx.x < nwarps) ? shared[threadIdx.x] : 0.0;
    if (wid == 0) {
        #pragma unroll
        for (int o = 16; o > 0; o >>= 1)
            val += __shfl_down_sync(0xffffffffu, val, o);
    }
    return val;  // valid on thread 0
}

// ---------------- K1: fused O(N^2) pair kernel (packed f32x2) ----------------
__global__ __launch_bounds__(TPB2) void k_pairs(const float* __restrict__ a,
                                                const float* __restrict__ b,
                                                const float* __restrict__ w, int n) {
    // reset ticket for k_rowred (stream-ordered: all rowred blocks run after this kernel)
    if (blockIdx.x == 0 && blockIdx.y == 0 && threadIdx.x == 0) g_counter = 0u;

    __shared__ u64 sna[JC], snb[JC], sw2[JC];   // pre-packed {-aj,-aj},{-bj,-bj},{wj,wj}
    const int tid   = threadIdx.x;
    const int jBase = blockIdx.x * JC;
    #pragma unroll
    for (int t = tid; t < JC; t += TPB2) {
        sna[t] = f2pack(-a[jBase + t]);
        snb[t] = f2pack(-b[jBase + t]);
        sw2[t] = f2pack(w[jBase + t]);
    }
    __syncthreads();

    const int iBase = blockIdx.y * (TPB2 * IT);
    u64 ai2[ITP], bi2[ITP], acc_uv[ITP], acc_a[ITP], acc_b[ITP];
    #pragma unroll
    for (int m = 0; m < ITP; m++) {
        int ilo = iBase + (2 * m) * TPB2 + tid;
        int ihi = iBase + (2 * m + 1) * TPB2 + tid;
        float alo = a[ilo], ahi = a[ihi];
        float blo = b[ilo], bhi = b[ihi];
        asm("mov.b64 %0, {%1, %2};" : "=l"(ai2[m]) : "f"(alo), "f"(ahi));
        asm("mov.b64 %0, {%1, %2};" : "=l"(bi2[m]) : "f"(blo), "f"(bhi));
        acc_uv[m] = 0ull; acc_a[m] = 0ull; acc_b[m] = 0ull;
    }

    #pragma unroll 4
    for (int j = 0; j < JC; j++) {
        u64 naj = sna[j], nbj = snb[j], wj2 = sw2[j];
        #pragma unroll
        for (int m = 0; m < ITP; m++) {
            u64 da = add2(ai2[m], naj);     // f32x2 sub
            u64 db = add2(bi2[m], nbj);
            da &= ABSMASK;                  // |.| : LOP3 (alu pipe)
            db &= ABSMASK;
            u64 t  = mul2(da, wj2);
            acc_a[m]  = add2(acc_a[m], t);
            acc_uv[m] = fma2(t, db, acc_uv[m]);
            acc_b[m]  = fma2(db, wj2, acc_b[m]);
        }
    }

    const int jc = blockIdx.x;
    double s = 0.0;
    #pragma unroll
    for (int m = 0; m < ITP; m++) {
        int ilo = iBase + (2 * m) * TPB2 + tid;
        int ihi = iBase + (2 * m + 1) * TPB2 + tid;
        float alo, ahi, blo, bhi, ulo, uhi;
        unpack2(acc_a[m], alo, ahi);
        unpack2(acc_b[m], blo, bhi);
        unpack2(acc_uv[m], ulo, uhi);
        g_apart[jc * n + ilo] = alo;  g_apart[jc * n + ihi] = ahi;
        g_bpart[jc * n + ilo] = blo;  g_bpart[jc * n + ihi] = bhi;
        s += (double)w[ilo] * (double)ulo + (double)w[ihi] * (double)uhi;
    }
    double r = blockReduceSumD(s);
    if (tid == 0) g_uvpart[blockIdx.y * gridDim.x + blockIdx.x] = r;
}

// ---------------- K2: row-sums + moments + last-block final ----------------
// sums order: 0:Sa 1:Sb 2:Sab 3:Saa 4:Sbb 5:W 6:Sbce 7:Saw 8:Sa2 9:Sew 10:Se2
__global__ __launch_bounds__(RTPB) void k_rowred(const float* __restrict__ x,
                                                 const float* __restrict__ y,
                                                 const float* __restrict__ e,
                                                 const float* __restrict__ w,
                                                 float* __restrict__ out, int n) {
    const int tid  = threadIdx.x;
    const int lane = tid & 31;
    const int wid  = tid >> 5;
    const int i    = blockIdx.x * RTPB + tid;

    // alpha'/beta' row totals — NJC=8 partials each, fully unrolled (16 loads)
    float a1 = 0.f, b1 = 0.f;
    #pragma unroll
    for (int jc = 0; jc < NJC; jc++) {
        a1 += g_apart[jc * n + i];
        b1 += g_bpart[jc * n + i];
    }

    const float xi = x[i], yi = y[i], ei = e[i], wi = w[i];
    const float sp = fmaxf(xi, 0.f) + log1pf(expf(-fabsf(xi)));  // softplus

    const double ad = (double)a1, bd = (double)b1, wd = (double)wi;
    double v[NSUM];
    v[0]  = ad * wd;
    v[1]  = bd * wd;
    v[2]  = ad * bd * wd;
    v[3]  = ad * ad * wd;
    v[4]  = bd * bd * wd;
    v[5]  = wd;
    v[6]  = (double)((sp - xi * yi) * wi);
    v[7]  = (double)xi * wd;
    v[8]  = (double)xi * (double)xi * wd;
    v[9]  = (double)ei * wd;
    v[10] = (double)ei * (double)ei * wd;

    // interleaved warp reduction of all 11 sums (latency overlapped)
    #pragma unroll
    for (int o = 16; o > 0; o >>= 1) {
        #pragma unroll
        for (int c = 0; c < NSUM; c++)
            v[c] += __shfl_down_sync(0xffffffffu, v[c], o);
    }

    __shared__ double warpsums[RWARPS][NSUM];
    if (lane == 0) {
        #pragma unroll
        for (int c = 0; c < NSUM; c++) warpsums[wid][c] = v[c];
    }
    __syncthreads();

    if (tid < NSUM) {
        double s = 0.0;
        #pragma unroll
        for (int w2 = 0; w2 < RWARPS; w2++) s += warpsums[w2][tid];
        g_red[blockIdx.x * NSUM + tid] = s;
    }

    // ---- last-block final combine ----
    __shared__ bool amLast;
    __syncthreads();          // all g_red stores issued before any thread tickets
    __threadfence();
    if (tid == 0) {
        unsigned int ticket = atomicAdd(&g_counter, 1u);
        amLast = (ticket == gridDim.x - 1);
    }
    __syncthreads();
    if (!amLast) return;
    __threadfence();

    __shared__ double sres[NSUM + 1];

    // S_uv over NUV=128 pair-block partials (guarded: NUV < RTPB)
    double s = (tid < NUV) ? g_uvpart[tid] : 0.0;
    double r = blockReduceSumD(s);
    if (tid == 0) sres[0] = r;

    // 8 warps cover 11 scalars (warps 0-2 take two each): warp reduces the
    // 32 block-partials (RBLK == 32 == warp size) of scalar c.
    for (int c = wid; c < NSUM; c += RWARPS) {
        double vv = g_red[lane * NSUM + c];
        #pragma unroll
        for (int o = 16; o > 0; o >>= 1)
            vv += __shfl_down_sync(0xffffffffu, vv, o);
        if (lane == 0) sres[1 + c] = vv;
    }
    __syncthreads();

    if (tid == 0) {
        const double Suv = sres[0];
        const double Sa  = sres[1];
        const double Sb  = sres[2];
        const double Sab = sres[3];
        const double Saa = sres[4];
        const double Sbb = sres[5];
        const double W   = sres[6];
        const double Sbce= sres[7];
        const double Saw = sres[8];
        const double Sa2 = sres[9];
        const double Sew = sres[10];
        const double Se2 = sres[11];

        const double W2 = W * W, W3 = W2 * W, W4 = W2 * W2;

        double num  = Suv / W2 - 2.0 * Sab / W3 + (Sa * Sb) / W4;
        double denA = 2.0 * (W * Sa2 - Saw * Saw) / W2 - 2.0 * Saa / W3 + (Sa * Sa) / W4;
        double denB = 2.0 * (W * Se2 - Sew * Sew) / W2 - 2.0 * Sbb / W3 + (Sb * Sb) / W4;

        double disco = num / sqrt(denA * denB);
        double bce   = Sbce / (double)n;

        out[0] = (float)bce;
        out[1] = (float)disco;
        out[2] = (float)(bce + 0.1 * disco);
    }
}

// ---------------- launch ----------------
extern "C" void kernel_launch(void* const* d_in, const int* in_sizes, int n_in,
                              void* d_out, int out_size) {
    const float* outputs = (const float*)d_in[0];
    const float* labels  = (const float*)d_in[1];
    const float* event   = (const float*)d_in[2];
    const float* weights = (const float*)d_in[3];
    float* out = (float*)d_out;
    const int n = in_sizes[0];   // 8192

    dim3 g2(n / JC, n / (TPB2 * IT));   // (8, 16) = 128 blocks
    k_pairs<<<g2, TPB2>>>(outputs, event, weights, n);

    k_rowred<<<n / RTPB, RTPB>>>(outputs, labels, event, weights, out, n);
}

// round 8
// speedup vs baseline: 1.2252x; 1.2252x over previous
#include <cuda_runtime.h>
#include <math.h>

// ---------------- configuration ----------------
#define TPB  128      // threads per block
#define IT   4        // i's per thread (2 packed f32x2 lanes)
#define ITP  (IT/2)   // packed accumulators per thread
#define JC   128      // j-chunk size (smem tile)
#define MAXN 8192
#define NJC  (MAXN / JC)                  // 64 j-chunks
#define NIG  (MAXN / (TPB * IT))          // 16 i-groups
#define NBLK (NJC * NIG)                  // 1024 blocks total (all co-resident)
#define NUV  NBLK                         // 1024 uv partials
#define P2B  64                           // phase-2 blocks (rows: 64*128 = 8192)
#define NSUM 11
#define ABSMASK 0x7FFFFFFF7FFFFFFFULL

// ---------------- device scratch (static, no allocation) ----------------
__device__ float  g_apart[NJC * MAXN];     // per-(jchunk,i) partial of alpha'
__device__ float  g_bpart[NJC * MAXN];     // per-(jchunk,i) partial of beta'
__device__ double g_uvpart[NUV];           // per-block partial of S_uv
__device__ double g_red[P2B * NSUM];       // per-phase2-block partial sums
__device__ volatile unsigned int g_bar1 = 0;  // phase-1 arrivals
__device__ unsigned int g_bar2 = 0;           // phase-2 ticket

// ---------------- f32x2 helpers ----------------
typedef unsigned long long u64;

__device__ __forceinline__ u64 f2pack(float x) {
    u64 r; asm("mov.b64 %0, {%1, %1};" : "=l"(r) : "f"(x)); return r;
}
__device__ __forceinline__ u64 add2(u64 a, u64 b) {
    u64 r; asm("add.rn.f32x2 %0, %1, %2;" : "=l"(r) : "l"(a), "l"(b)); return r;
}
__device__ __forceinline__ u64 mul2(u64 a, u64 b) {
    u64 r; asm("mul.rn.f32x2 %0, %1, %2;" : "=l"(r) : "l"(a), "l"(b)); return r;
}
__device__ __forceinline__ u64 fma2(u64 a, u64 b, u64 c) {
    u64 r; asm("fma.rn.f32x2 %0, %1, %2, %3;" : "=l"(r) : "l"(a), "l"(b), "l"(c)); return r;
}
__device__ __forceinline__ void unpack2(u64 v, float& lo, float& hi) {
    asm("mov.b64 {%0, %1}, %2;" : "=f"(lo), "=f"(hi) : "l"(v));
}

// ---------------- block reduction (double), 128 threads ----------------
__device__ __forceinline__ double blockReduceSumD(double val) {
    __shared__ double shared[4];
    __syncthreads();
    int lane = threadIdx.x & 31;
    int wid  = threadIdx.x >> 5;
    #pragma unroll
    for (int o = 16; o > 0; o >>= 1)
        val += __shfl_down_sync(0xffffffffu, val, o);
    if (lane == 0) shared[wid] = val;
    __syncthreads();
    if (wid == 0) {
        val = (lane < 4) ? shared[lane] : 0.0;
        #pragma unroll
        for (int o = 2; o > 0; o >>= 1)
            val += __shfl_down_sync(0xffffffffu, val, o);
    }
    return val;  // valid on thread 0
}

// ---------------- single fused kernel ----------------
__global__ __launch_bounds__(TPB, 7) void k_all(const float* __restrict__ a,    // outputs
                                                const float* __restrict__ y,    // labels
                                                const float* __restrict__ b,    // event
                                                const float* __restrict__ w,    // weights
                                                float* __restrict__ out, int n) {
    const int tid = threadIdx.x;
    const int bid = blockIdx.y * gridDim.x + blockIdx.x;

    // ================= PHASE 1: pair compute =================
    __shared__ u64 sna[JC], snb[JC], sw2[JC];
    const int jBase = blockIdx.x * JC;
    // JC == TPB: one element per thread
    sna[tid] = f2pack(-a[jBase + tid]);
    snb[tid] = f2pack(-b[jBase + tid]);
    sw2[tid] = f2pack(w[jBase + tid]);
    __syncthreads();

    const int iBase = blockIdx.y * (TPB * IT);
    u64 ai2[ITP], bi2[ITP], acc_uv[ITP], acc_a[ITP], acc_b[ITP];
    #pragma unroll
    for (int m = 0; m < ITP; m++) {
        int ilo = iBase + (2 * m) * TPB + tid;
        int ihi = iBase + (2 * m + 1) * TPB + tid;
        float alo = a[ilo], ahi = a[ihi];
        float blo = b[ilo], bhi = b[ihi];
        asm("mov.b64 %0, {%1, %2};" : "=l"(ai2[m]) : "f"(alo), "f"(ahi));
        asm("mov.b64 %0, {%1, %2};" : "=l"(bi2[m]) : "f"(blo), "f"(bhi));
        acc_uv[m] = 0ull; acc_a[m] = 0ull; acc_b[m] = 0ull;
    }

    #pragma unroll 4
    for (int j = 0; j < JC; j++) {
        u64 naj = sna[j], nbj = snb[j], wj2 = sw2[j];
        #pragma unroll
        for (int m = 0; m < ITP; m++) {
            u64 da = add2(ai2[m], naj);
            u64 db = add2(bi2[m], nbj);
            da &= ABSMASK;
            db &= ABSMASK;
            u64 t  = mul2(da, wj2);
            acc_a[m]  = add2(acc_a[m], t);
            acc_uv[m] = fma2(t, db, acc_uv[m]);
            acc_b[m]  = fma2(db, wj2, acc_b[m]);
        }
    }

    const int jc = blockIdx.x;
    {
        double s = 0.0;
        #pragma unroll
        for (int m = 0; m < ITP; m++) {
            int ilo = iBase + (2 * m) * TPB + tid;
            int ihi = iBase + (2 * m + 1) * TPB + tid;
            float alo, ahi, blo, bhi, ulo, uhi;
            unpack2(acc_a[m], alo, ahi);
            unpack2(acc_b[m], blo, bhi);
            unpack2(acc_uv[m], ulo, uhi);
            g_apart[jc * n + ilo] = alo;  g_apart[jc * n + ihi] = ahi;
            g_bpart[jc * n + ilo] = blo;  g_bpart[jc * n + ihi] = bhi;
            s += (double)w[ilo] * (double)ulo + (double)w[ihi] * (double)uhi;
        }
        double r = blockReduceSumD(s);
        if (tid == 0) g_uvpart[bid] = r;
    }

    // ================= GRID BARRIER =================
    __syncthreads();            // all stores of this block issued
    __threadfence();            // visible GPU-wide
    if (tid == 0) atomicAdd((unsigned int*)&g_bar1, 1u);

    if (bid >= P2B) return;     // non-participants exit (frees SM slots)

    if (tid == 0) {
        while (g_bar1 < (unsigned int)NBLK) { /* spin */ }
    }
    __syncthreads();
    __threadfence();            // acquire: see all blocks' scratch stores

    // ================= PHASE 2: row reduce (one row per thread) =================
    const int lane = tid & 31;
    const int wid  = tid >> 5;
    const int i    = bid * TPB + tid;

    float a1 = 0.f, b1 = 0.f;
    #pragma unroll 8
    for (int c = 0; c < NJC; c++) {
        a1 += g_apart[c * n + i];
        b1 += g_bpart[c * n + i];
    }

    const float xi = a[i], yi = y[i], ei = b[i], wi = w[i];
    const float sp = fmaxf(xi, 0.f) + log1pf(expf(-fabsf(xi)));  // softplus

    const double ad = (double)a1, bd = (double)b1, wd = (double)wi;
    double v[NSUM];
    v[0]  = ad * wd;
    v[1]  = bd * wd;
    v[2]  = ad * bd * wd;
    v[3]  = ad * ad * wd;
    v[4]  = bd * bd * wd;
    v[5]  = wd;
    v[6]  = (double)((sp - xi * yi) * wi);
    v[7]  = (double)xi * wd;
    v[8]  = (double)xi * (double)xi * wd;
    v[9]  = (double)ei * wd;
    v[10] = (double)ei * (double)ei * wd;

    // interleaved warp reduction of all 11 sums
    #pragma unroll
    for (int o = 16; o > 0; o >>= 1) {
        #pragma unroll
        for (int c = 0; c < NSUM; c++)
            v[c] += __shfl_down_sync(0xffffffffu, v[c], o);
    }

    __shared__ double warpsums[TPB / 32][NSUM];
    if (lane == 0) {
        #pragma unroll
        for (int c = 0; c < NSUM; c++) warpsums[wid][c] = v[c];
    }
    __syncthreads();

    if (tid < NSUM) {
        double s = 0.0;
        #pragma unroll
        for (int w2 = 0; w2 < TPB / 32; w2++) s += warpsums[w2][tid];
        g_red[bid * NSUM + tid] = s;
    }

    // ---- ticket among the P2B phase-2 blocks ----
    __shared__ bool amLast;
    __syncthreads();
    __threadfence();
    if (tid == 0) {
        unsigned int ticket = atomicAdd(&g_bar2, 1u);
        amLast = (ticket == P2B - 1);
    }
    __syncthreads();
    if (!amLast) return;
    __threadfence();

    // ================= FINAL COMBINE (one block) =================
    __shared__ double sres[NSUM + 1];

    // S_uv over 1024 partials: 8 per thread
    double s = 0.0;
    #pragma unroll
    for (int k = 0; k < NUV / TPB; k++) s += g_uvpart[k * TPB + tid];
    double r = blockReduceSumD(s);
    if (tid == 0) sres[0] = r;

    // 4 warps cover 11 scalars; each warp reduces 64 block-partials of scalar c
    for (int c = wid; c < NSUM; c += TPB / 32) {
        double vv = g_red[lane * NSUM + c] + g_red[(lane + 32) * NSUM + c];
        #pragma unroll
        for (int o = 16; o > 0; o >>= 1)
            vv += __shfl_down_sync(0xffffffffu, vv, o);
        if (lane == 0) sres[1 + c] = vv;
    }
    __syncthreads();

    if (tid == 0) {
        const double Suv = sres[0];
        const double Sa  = sres[1];
        const double Sb  = sres[2];
        const double Sab = sres[3];
        const double Saa = sres[4];
        const double Sbb = sres[5];
        const double W   = sres[6];
        const double Sbce= sres[7];
        const double Saw = sres[8];
        const double Sa2 = sres[9];
        const double Sew = sres[10];
        const double Se2 = sres[11];

        const double W2 = W * W, W3 = W2 * W, W4 = W2 * W2;

        double num  = Suv / W2 - 2.0 * Sab / W3 + (Sa * Sb) / W4;
        double denA = 2.0 * (W * Sa2 - Saw * Saw) / W2 - 2.0 * Saa / W3 + (Sa * Sa) / W4;
        double denB = 2.0 * (W * Se2 - Sew * Sew) / W2 - 2.0 * Sbb / W3 + (Sb * Sb) / W4;

        double disco = num / sqrt(denA * denB);
        double bce   = Sbce / (double)n;

        out[0] = (float)bce;
        out[1] = (float)disco;
        out[2] = (float)(bce + 0.1 * disco);

        // reset barriers for the next (graph-replayed) invocation.
        // Safe: all NBLK blocks have arrived (bar1 spin passed) and all P2B
        // phase-2 blocks have ticketed (we are the last). No one reads after.
        g_bar1 = 0u;
        g_bar2 = 0u;
    }
}

// ---------------- launch ----------------
extern "C" void kernel_launch(void* const* d_in, const int* in_sizes, int n_in,
                              void* d_out, int out_size) {
    const float* outputs = (const float*)d_in[0];
    const float* labels  = (const float*)d_in[1];
    const float* event   = (const float*)d_in[2];
    const float* weights = (const float*)d_in[3];
    float* out = (float*)d_out;
    const int n = in_sizes[0];   // 8192

    dim3 g(NJC, NIG);   // (64, 16) = 1024 blocks, all co-resident
    k_all<<<g, TPB>>>(outputs, labels, event, weights, out, n);
}